// round 13
// baseline (speedup 1.0000x reference)
#include <cuda_runtime.h>
#include <cuda_bf16.h>
#include <math.h>

#define B_    256
#define L_    512
#define D_    512
#define NROWS (B_ * L_)     // 131072
#define NBLK  2048          // 64-row blocks
#define LN2_F     0.6931471805599453f
#define INV_LN2_F 1.4426950408889634f

// ---------------- device scratch (no allocs allowed) ----------------
__device__ __align__(16) float    g_u[B_ * D_];       // image_proj [k][e]
__device__ __align__(16) float    g_WMLT[D_ * D_];    // W_ML^T [d][e]
__device__ __align__(16) float    g_vT[D_ * B_];      // v^T [d][k], v = (u@W_ML)/(tau*ln2)
__device__ unsigned g_maskT[L_ * 8];                  // per l: 256-bit valid-over-k
__device__ float    g_siji[NROWS];                    // base-2 scores
__device__ float    g_denom[NROWS];                   // base-2 LSE
__device__ float    g_pm[NBLK];                       // per-block shift (base-2)
__device__ float    g_ps[(size_t)B_ * NBLK];          // [col][blk] partial sums
__device__ float    g_cross[B_];                      // base-2
__device__ float    g_lsum[256];
__device__ float    g_lcnt[256];
__device__ int      g_mmode;

typedef unsigned long long ull;
__device__ __forceinline__ ull pk2(float x){ ull r; asm("mov.b64 %0,{%1,%1};":"=l"(r):"f"(x)); return r; }
__device__ __forceinline__ ull f2fma(ull a, ull b, ull c){
    ull d; asm("fma.rn.f32x2 %0,%1,%2,%3;":"=l"(d):"l"(a),"l"(b),"l"(c)); return d; }
__device__ __forceinline__ void upk(ull v, float& lo, float& hi){
    asm("mov.b64 {%0,%1},%2;":"=f"(lo),"=f"(hi):"l"(v)); }
__device__ __forceinline__ void cp16(void* dst, const void* src){
    unsigned d = (unsigned)__cvta_generic_to_shared(dst);
    asm volatile("cp.async.cg.shared.global [%0],[%1],16;"::"r"(d),"l"(src)); }

// ================= mask dtype detection =================
__global__ void detect_kernel(const unsigned char* __restrict__ p){
    __shared__ int c[4];
    int tid = threadIdx.x;
    if (tid < 4) c[tid] = 0;
    __syncthreads();
    int loc[4] = {0,0,0,0};
    for (int idx = tid; idx < 4096; idx += 256) if (p[idx]) loc[idx & 3] = 1;
    #pragma unroll
    for (int j = 0; j < 4; ++j) if (loc[j]) atomicOr(&c[j], 1);
    __syncthreads();
    if (tid == 0){
        int mode;
        if (c[1]) mode = 0;          // bytes at %4==1 nonzero -> uint8 bool
        else if (c[0]) mode = 1;     // only %4==0 nonzero -> int32 0/1
        else mode = 2;               // 1.0f pattern -> float32
        g_mmode = mode;
    }
}

__device__ __forceinline__ int mask_is_set(const unsigned char* p, int idx, int mode){
    if (mode == 0) return p[idx] != 0;
    if (mode == 1) return p[(size_t)idx * 4] != 0;
    return p[(size_t)idx * 4 + 2] != 0;
}

// ================= prep: transpose W_ML + build valid bitmaps =================
__global__ void prep_kernel(const float* __restrict__ W_ML,
                            const unsigned char* __restrict__ pmask){
    int t = blockIdx.x * blockDim.x + threadIdx.x;
    if (t < D_ * D_){
        int d = t >> 9, e = t & 511;
        g_WMLT[t] = W_ML[e * D_ + d];
    }
    if (t < L_ * 8){
        int mode = g_mmode;
        int l = t >> 3, w = t & 7;
        unsigned bits = 0;
        for (int kb = 0; kb < 32; ++kb){
            int k = w * 32 + kb;
            if (!mask_is_set(pmask, k * L_ + l, mode)) bits |= (1u << kb);
        }
        g_maskT[t] = bits;
    }
}

// ================= fast small NT GEMM body: 32x64 tile, vectorized smem =================
// C[m,n] = scale * sum_k A[m,k] * B[n,k]
// Called ONLY from __global__ wrappers (device symbols must resolve in device code).
__device__ __forceinline__ void gemm_body(
        const float* __restrict__ A, const float* __restrict__ Bm,
        float* __restrict__ C, int K, int Mtot, int Ntot,
        float baseScale, const float* __restrict__ tauPtr, int transOut){
    __shared__ float Ask[32 * 34];
    __shared__ float Bsk[32 * 68];
    int tid = threadIdx.x;
    int row0 = blockIdx.x * 32, col0 = blockIdx.y * 64;
    int rg = tid >> 4, cg = tid & 15;
    int am = tid >> 3, aq = tid & 7;
    float acc[2][4] = {};
    float4 ra[2], rb0[2], rb1[2];

    ra[0]  = *(const float4*)(A  + (size_t)(row0 + am) * K + aq * 4);
    rb0[0] = *(const float4*)(Bm + (size_t)(col0 + am) * K + aq * 4);
    rb1[0] = *(const float4*)(Bm + (size_t)(col0 + 32 + am) * K + aq * 4);

    int NS = K / 32;
    #pragma unroll 1
    for (int s = 0; s < NS; ++s){
        float4 va = ra[s & 1], vb0 = rb0[s & 1], vb1 = rb1[s & 1];
        const float* pa = (const float*)&va;
        const float* p0 = (const float*)&vb0;
        const float* p1 = (const float*)&vb1;
        #pragma unroll
        for (int t = 0; t < 4; ++t){
            Ask[(aq * 4 + t) * 34 + am]      = pa[t];
            Bsk[(aq * 4 + t) * 68 + am]      = p0[t];
            Bsk[(aq * 4 + t) * 68 + 32 + am] = p1[t];
        }
        if (s + 1 < NS){
            int k0 = (s + 1) * 32;
            ra[(s+1)&1]  = *(const float4*)(A  + (size_t)(row0 + am) * K + k0 + aq * 4);
            rb0[(s+1)&1] = *(const float4*)(Bm + (size_t)(col0 + am) * K + k0 + aq * 4);
            rb1[(s+1)&1] = *(const float4*)(Bm + (size_t)(col0 + 32 + am) * K + k0 + aq * 4);
        }
        __syncthreads();
        #pragma unroll
        for (int kk = 0; kk < 32; ++kk){
            float2 a = *(const float2*)&Ask[kk * 34 + rg * 2];
            float4 b = *(const float4*)&Bsk[kk * 68 + cg * 4];
            acc[0][0] = fmaf(a.x, b.x, acc[0][0]);
            acc[0][1] = fmaf(a.x, b.y, acc[0][1]);
            acc[0][2] = fmaf(a.x, b.z, acc[0][2]);
            acc[0][3] = fmaf(a.x, b.w, acc[0][3]);
            acc[1][0] = fmaf(a.y, b.x, acc[1][0]);
            acc[1][1] = fmaf(a.y, b.y, acc[1][1]);
            acc[1][2] = fmaf(a.y, b.z, acc[1][2]);
            acc[1][3] = fmaf(a.y, b.w, acc[1][3]);
        }
        __syncthreads();
    }
    float sc = baseScale;
    if (tauPtr) sc = INV_LN2_F / fmaxf(tauPtr[0], 0.001f);
    #pragma unroll
    for (int i = 0; i < 2; ++i)
        #pragma unroll
        for (int j = 0; j < 4; ++j){
            int m = row0 + rg * 2 + i, n = col0 + cg * 4 + j;
            float v = acc[i][j] * sc;
            if (transOut) C[(size_t)n * Mtot + m] = v;
            else          C[(size_t)m * Ntot + n] = v;
        }
}

__global__ void __launch_bounds__(256) proj_u_kernel(
        const float* __restrict__ image, const float* __restrict__ W_MV){
    gemm_body(image, W_MV, g_u, D_, B_, D_, 1.0f, (const float*)0, 0);
}
__global__ void __launch_bounds__(256) proj_v_kernel(const float* __restrict__ tau){
    gemm_body(g_u, g_WMLT, g_vT, D_, B_, D_, 1.0f, tau, 1);   // writes vT[d][k]
}

// ================= main: S/ln2 = TEXT @ v^T + fused masked base-2 LSE =================
// BK=16. A tile stored in smem pre-duplicated (ull per scalar), stride 17 ull.
// B triple-buffered via cp.async; A double-buffered via LDG regs + STS.
#define BFLOATS 4096                      // 16*256 floats per B buffer
#define AULL    (64 * 17)                 // per A buffer (ull)
#define SMEM_BYTES (3 * BFLOATS * 4 + 2 * AULL * 8)   // 66560

__global__ void __launch_bounds__(256, 2) main_kernel(const float* __restrict__ text){
    extern __shared__ float sm[];
    float* Bbuf[3] = { sm, sm + BFLOATS, sm + 2 * BFLOATS };
    ull* Abase = (ull*)(sm + 3 * BFLOATS);
    ull* Abuf[2] = { Abase, Abase + AULL };

    const int tid   = threadIdx.x;
    const int blk   = blockIdx.x;
    const int r0    = blk * 64;
    const int i_blk = blk >> 3;
    const int ty    = tid >> 5;
    const int tx    = tid & 31;
    const int arow  = tid >> 2;            // 0..63
    const int aq    = tid & 3;             // quad of 4 floats

    ull acc[8][4];
    #pragma unroll
    for (int j = 0; j < 8; ++j)
        #pragma unroll
        for (int c = 0; c < 4; ++c) acc[j][c] = 0ULL;

    // ---- prologue ----
    float4 areg[2];
    areg[0] = *(const float4*)(text + (size_t)(r0 + arow) * D_ + aq * 4);
    areg[1] = *(const float4*)(text + (size_t)(r0 + arow) * D_ + 16 + aq * 4);
    {   // STS dup A0
        const float* pv = (const float*)&areg[0];
        int base = arow * 17 + aq * 4;
        #pragma unroll
        for (int t = 0; t < 4; ++t) Abuf[0][base + t] = pk2(pv[t]);
    }
    #pragma unroll
    for (int half = 0; half < 2; ++half){   // B0, B1
        float* Bd = Bbuf[half];
        int k0 = half * 16;
        #pragma unroll
        for (int it = 0; it < 4; ++it){
            int f = tid * 4 + it; int kk = f >> 6, j4 = (f & 63) * 4;
            cp16(Bd + kk * 256 + j4, g_vT + (size_t)(k0 + kk) * B_ + j4);
        }
        asm volatile("cp.async.commit_group;":::"memory");
    }

    int bcur = 0;
    #pragma unroll 1
    for (int itn = 0; itn < 32; ++itn){
        if (itn < 31) asm volatile("cp.async.wait_group 1;":::"memory");
        else          asm volatile("cp.async.wait_group 0;":::"memory");
        __syncthreads();
        if (itn + 1 < 32){
            const float* pv = (const float*)&areg[(itn + 1) & 1];
            ull* Ad = Abuf[(itn + 1) & 1];
            int base = arow * 17 + aq * 4;
            #pragma unroll
            for (int t = 0; t < 4; ++t) Ad[base + t] = pk2(pv[t]);
        }
        if (itn + 2 < 32){
            int k0 = (itn + 2) * 16;
            areg[(itn + 2) & 1] = *(const float4*)(text + (size_t)(r0 + arow) * D_ + k0 + aq * 4);
            int bfill = bcur + 2; if (bfill >= 3) bfill -= 3;
            float* Bd = Bbuf[bfill];
            #pragma unroll
            for (int it = 0; it < 4; ++it){
                int f = tid * 4 + it; int kk = f >> 6, j4 = (f & 63) * 4;
                cp16(Bd + kk * 256 + j4, g_vT + (size_t)(k0 + kk) * B_ + j4);
            }
            asm volatile("cp.async.commit_group;":::"memory");
        }
        const ull* Ad = Abuf[itn & 1];
        const ulonglong2* Bv = (const ulonglong2*)Bbuf[bcur];
        #pragma unroll
        for (int kk = 0; kk < 16; ++kk){
            ull a2[8];
            #pragma unroll
            for (int j = 0; j < 8; ++j) a2[j] = Ad[(ty * 8 + j) * 17 + kk];  // warp-uniform LDS.64
            #pragma unroll
            for (int g = 0; g < 2; ++g){
                ulonglong2 bb = Bv[kk * 64 + g * 32 + tx];                   // LDS.128
                #pragma unroll
                for (int j = 0; j < 8; ++j){
                    acc[j][g*2]   = f2fma(a2[j], bb.x, acc[j][g*2]);
                    acc[j][g*2+1] = f2fma(a2[j], bb.y, acc[j][g*2+1]);
                }
            }
        }
        if (++bcur == 3) bcur = 0;
    }
    __syncthreads();

    // -------- epilogue (smem reuse), base-2 domain --------
    unsigned* smk  = (unsigned*)sm;   // 512 mask words (64 rows x 8)
    float*    wmx  = sm + 512;        // 8 per-warp shifts
    float*    stage= sm + 528;        // 8 x 256 column partials

    smk[tid]       = g_maskT[(blk & 7) * 512 + tid];
    smk[tid + 256] = g_maskT[(blk & 7) * 512 + 256 + tid];
    __syncthreads();

    const int sg = i_blk >> 7, srem = i_blk & 127;
    const bool sown = (tx == (srem >> 2));
    const int  scc  = sg * 4 + (srem & 3);

    // pass 1: per-row full max (valid shift for everything), s_iji
    float mr[8];
    #pragma unroll
    for (int j = 0; j < 8; ++j){
        float f[8];
        #pragma unroll
        for (int c = 0; c < 4; ++c) upk(acc[j][c], f[c*2], f[c*2+1]);
        float mx = f[0];
        #pragma unroll
        for (int c = 1; c < 8; ++c) mx = fmaxf(mx, f[c]);
        #pragma unroll
        for (int o = 16; o >= 1; o >>= 1) mx = fmaxf(mx, __shfl_xor_sync(0xffffffffu, mx, o));
        mr[j] = mx;
        if (sown) g_siji[r0 + ty * 8 + j] = f[scc];
    }
    float Mw = mr[0];
    #pragma unroll
    for (int j = 1; j < 8; ++j) Mw = fmaxf(Mw, mr[j]);

    // pass 2: ONE exp2 per element serves row-LSE (k-mask) and column partials (row-valid)
    float colacc[8];
    #pragma unroll
    for (int c = 0; c < 8; ++c) colacc[c] = 0.f;
    const int iw = i_blk >> 5, ib = i_blk & 31;

    #pragma unroll
    for (int j = 0; j < 8; ++j){
        int R = ty * 8 + j;
        unsigned w0 = smk[R*8 + (tx >> 3)];
        unsigned w1 = smk[R*8 + 4 + (tx >> 3)];
        float rv = (float)((smk[R*8 + iw] >> ib) & 1u);
        float f[8];
        #pragma unroll
        for (int c = 0; c < 4; ++c) upk(acc[j][c], f[c*2], f[c*2+1]);
        float rsum = 0.f;
        #pragma unroll
        for (int c = 0; c < 8; ++c){
            float e = exp2f(f[c] - Mw);
            unsigned wg = (c < 4) ? w0 : w1;
            int q = c & 3;
            unsigned bit = (wg >> ((tx & 7) * 4 + q)) & 1u;
            rsum += bit ? e : 0.f;
            colacc[c] += rv * e;
        }
        #pragma unroll
        for (int o = 16; o >= 1; o >>= 1) rsum += __shfl_xor_sync(0xffffffffu, rsum, o);
        if (tx == 0) g_denom[r0 + R] = Mw + log2f(rsum);
    }

    if (tx == 0) wmx[ty] = Mw;
    #pragma unroll
    for (int c = 0; c < 8; ++c){
        int g = c >> 2, q = c & 3;
        stage[ty * 256 + g * 128 + tx * 4 + q] = colacc[c];
    }
    __syncthreads();

    {
        float Mb = wmx[0];
        #pragma unroll
        for (int t = 1; t < 8; ++t) Mb = fmaxf(Mb, wmx[t]);
        float S = 0.f;
        #pragma unroll
        for (int t = 0; t < 8; ++t) S += stage[t * 256 + tid] * exp2f(wmx[t] - Mb);
        g_ps[(size_t)tid * NBLK + blk] = S;
        if (tid == 0) g_pm[blk] = Mb;
    }
}

// ================= cross LSE per image column (skip same-batch blocks), base-2 =================
__global__ void cross_kernel(){
    int k = blockIdx.x, tid = threadIdx.x;
    float m = -INFINITY, s = 0.f;
    for (int b = tid; b < NBLK; b += 256){
        if ((b >> 3) == k) continue;
        float pm = g_pm[b], ps = g_ps[(size_t)k * NBLK + b];
        if (pm > m){ s = s * exp2f(m - pm) + ps; m = pm; }
        else       { s += ps * exp2f(pm - m); }
    }
    __shared__ float smm[256], sms[256];
    smm[tid] = m; sms[tid] = s;
    __syncthreads();
    for (int o = 128; o >= 1; o >>= 1){
        if (tid < o){
            float m1 = smm[tid], s1 = sms[tid];
            float m2 = smm[tid+o], s2 = sms[tid+o];
            if (m2 > m1){ s1 = s1 * exp2f(m1 - m2) + s2; m1 = m2; }
            else        { s1 += s2 * exp2f(m2 - m1); }
            smm[tid] = m1; sms[tid] = s1;
        }
        __syncthreads();
    }
    if (tid == 0) g_cross[k] = smm[0] + log2f(sms[0]);
}

// ================= final loss accumulation (convert base-2 -> natural) =================
__global__ void loss_kernel(){
    int tid = threadIdx.x;
    int r = blockIdx.x * 512 + tid;
    int i = r >> 9, l = r & 511;
    unsigned w = g_maskT[l*8 + (i >> 5)];
    int valid = (w >> (i & 31)) & 1;
    float ls = 0.f, lc = 0.f;
    if (valid){
        float s2 = g_siji[r], d2 = g_denom[r], c2 = g_cross[i];
        float mx = fmaxf(s2, c2), mn = fminf(s2, c2);
        float nl2 = mx + log1pf(exp2f(mn - mx)) * INV_LN2_F;   // log2(2^s2 + 2^c2)
        ls = 0.5f * LN2_F * ((d2 - s2) + (nl2 - s2));
        lc = 1.f;
    }
    __shared__ float rs[512], rc[512];
    rs[tid] = ls; rc[tid] = lc;
    __syncthreads();
    for (int o = 256; o >= 1; o >>= 1){
        if (tid < o){ rs[tid] += rs[tid+o]; rc[tid] += rc[tid+o]; }
        __syncthreads();
    }
    if (tid == 0){ g_lsum[blockIdx.x] = rs[0]; g_lcnt[blockIdx.x] = rc[0]; }
}

__global__ void finish_kernel(float* __restrict__ out){
    int tid = threadIdx.x;
    __shared__ float rs[256], rc[256];
    rs[tid] = g_lsum[tid]; rc[tid] = g_lcnt[tid];
    __syncthreads();
    for (int o = 128; o >= 1; o >>= 1){
        if (tid < o){ rs[tid] += rs[tid+o]; rc[tid] += rc[tid+o]; }
        __syncthreads();
    }
    if (tid == 0) out[0] = rs[0] / rc[0];
}

// ================= launch =================
extern "C" void kernel_launch(void* const* d_in, const int* in_sizes, int n_in,
                              void* d_out, int out_size){
    const float* text  = (const float*)d_in[0];
    const float* image = (const float*)d_in[1];
    const float* W_ML  = (const float*)d_in[2];
    const float* W_MV  = (const float*)d_in[3];
    const float* tau   = (const float*)d_in[4];
    const unsigned char* pmask = (const unsigned char*)d_in[5];
    float* out = (float*)d_out;

    detect_kernel<<<1, 256>>>(pmask);
    prep_kernel<<<1024, 256>>>(W_ML, pmask);
    proj_u_kernel<<<dim3(8, 8), 256>>>(image, W_MV);   // u = image @ W_MV^T
    proj_v_kernel<<<dim3(8, 8), 256>>>(tau);           // vT = ((u @ W_ML)/(tau*ln2))^T

    cudaFuncSetAttribute(main_kernel, cudaFuncAttributeMaxDynamicSharedMemorySize, SMEM_BYTES);
    main_kernel<<<NBLK, 256, SMEM_BYTES>>>(text);
    cross_kernel<<<256, 256>>>();
    loss_kernel<<<256, 512>>>();
    finish_kernel<<<1, 256>>>(out);
}

// round 15
// speedup vs baseline: 1.0036x; 1.0036x over previous
#include <cuda_runtime.h>
#include <cuda_bf16.h>
#include <math.h>

#define B_    256
#define L_    512
#define D_    512
#define NROWS (B_ * L_)     // 131072
#define NBLK  2048          // 64-row blocks
#define LN2_F     0.6931471805599453f
#define INV_LN2_F 1.4426950408889634f

// ---------------- device scratch (no allocs allowed) ----------------
__device__ __align__(16) float    g_u[B_ * D_];       // image_proj [k][e]
__device__ __align__(16) float    g_WMLT[D_ * D_];    // W_ML^T [d][e]
__device__ __align__(16) float    g_vT[D_ * B_];      // v^T [d][k], v = (u@W_ML)/(tau*ln2)
__device__ unsigned g_maskT[L_ * 8];                  // per l: 256-bit valid-over-k
__device__ float    g_siji[NROWS];                    // base-2 scores
__device__ float    g_denom[NROWS];                   // base-2 LSE
__device__ float    g_pm[NBLK];                       // per-block shift (base-2)
__device__ float    g_ps[(size_t)B_ * NBLK];          // [col][blk] partial sums
__device__ float    g_cross[B_];                      // base-2
__device__ float    g_lsum[256];
__device__ float    g_lcnt[256];
__device__ int      g_mmode;

typedef unsigned long long ull;
__device__ __forceinline__ ull pk2(float x){ ull r; asm("mov.b64 %0,{%1,%1};":"=l"(r):"f"(x)); return r; }
__device__ __forceinline__ ull f2fma(ull a, ull b, ull c){
    ull d; asm("fma.rn.f32x2 %0,%1,%2,%3;":"=l"(d):"l"(a),"l"(b),"l"(c)); return d; }
__device__ __forceinline__ void upk(ull v, float& lo, float& hi){
    asm("mov.b64 {%0,%1},%2;":"=f"(lo),"=f"(hi):"l"(v)); }
__device__ __forceinline__ void cp16(void* dst, const void* src){
    unsigned d = (unsigned)__cvta_generic_to_shared(dst);
    asm volatile("cp.async.cg.shared.global [%0],[%1],16;"::"r"(d),"l"(src)); }

// ================= mask dtype detection =================
__global__ void detect_kernel(const unsigned char* __restrict__ p){
    __shared__ int c[4];
    int tid = threadIdx.x;
    if (tid < 4) c[tid] = 0;
    __syncthreads();
    int loc[4] = {0,0,0,0};
    for (int idx = tid; idx < 4096; idx += 256) if (p[idx]) loc[idx & 3] = 1;
    #pragma unroll
    for (int j = 0; j < 4; ++j) if (loc[j]) atomicOr(&c[j], 1);
    __syncthreads();
    if (tid == 0){
        int mode;
        if (c[1]) mode = 0;          // bytes at %4==1 nonzero -> uint8 bool
        else if (c[0]) mode = 1;     // only %4==0 nonzero -> int32 0/1
        else mode = 2;               // 1.0f pattern -> float32
        g_mmode = mode;
    }
}

__device__ __forceinline__ int mask_is_set(const unsigned char* p, int idx, int mode){
    if (mode == 0) return p[idx] != 0;
    if (mode == 1) return p[(size_t)idx * 4] != 0;
    return p[(size_t)idx * 4 + 2] != 0;
}

// ================= prep: transpose W_ML + build valid bitmaps =================
__global__ void prep_kernel(const float* __restrict__ W_ML,
                            const unsigned char* __restrict__ pmask){
    int t = blockIdx.x * blockDim.x + threadIdx.x;
    if (t < D_ * D_){
        int d = t >> 9, e = t & 511;
        g_WMLT[t] = W_ML[e * D_ + d];
    }
    if (t < L_ * 8){
        int mode = g_mmode;
        int l = t >> 3, w = t & 7;
        unsigned bits = 0;
        for (int kb = 0; kb < 32; ++kb){
            int k = w * 32 + kb;
            if (!mask_is_set(pmask, k * L_ + l, mode)) bits |= (1u << kb);
        }
        g_maskT[t] = bits;
    }
}

// ================= fast small NT GEMM body: 32x64 tile, vectorized smem =================
// C[m,n] = scale * sum_k A[m,k] * B[n,k]
// Called ONLY from __global__ wrappers (device symbols must resolve in device code).
__device__ __forceinline__ void gemm_body(
        const float* __restrict__ A, const float* __restrict__ Bm,
        float* __restrict__ C, int K, int Mtot, int Ntot,
        float baseScale, const float* __restrict__ tauPtr, int transOut){
    __shared__ float Ask[32 * 34];
    __shared__ float Bsk[32 * 68];
    int tid = threadIdx.x;
    int row0 = blockIdx.x * 32, col0 = blockIdx.y * 64;
    int rg = tid >> 4, cg = tid & 15;
    int am = tid >> 3, aq = tid & 7;
    float acc[2][4] = {};
    float4 ra[2], rb0[2], rb1[2];

    ra[0]  = *(const float4*)(A  + (size_t)(row0 + am) * K + aq * 4);
    rb0[0] = *(const float4*)(Bm + (size_t)(col0 + am) * K + aq * 4);
    rb1[0] = *(const float4*)(Bm + (size_t)(col0 + 32 + am) * K + aq * 4);

    int NS = K / 32;
    #pragma unroll 1
    for (int s = 0; s < NS; ++s){
        float4 va = ra[s & 1], vb0 = rb0[s & 1], vb1 = rb1[s & 1];
        const float* pa = (const float*)&va;
        const float* p0 = (const float*)&vb0;
        const float* p1 = (const float*)&vb1;
        #pragma unroll
        for (int t = 0; t < 4; ++t){
            Ask[(aq * 4 + t) * 34 + am]      = pa[t];
            Bsk[(aq * 4 + t) * 68 + am]      = p0[t];
            Bsk[(aq * 4 + t) * 68 + 32 + am] = p1[t];
        }
        if (s + 1 < NS){
            int k0 = (s + 1) * 32;
            ra[(s+1)&1]  = *(const float4*)(A  + (size_t)(row0 + am) * K + k0 + aq * 4);
            rb0[(s+1)&1] = *(const float4*)(Bm + (size_t)(col0 + am) * K + k0 + aq * 4);
            rb1[(s+1)&1] = *(const float4*)(Bm + (size_t)(col0 + 32 + am) * K + k0 + aq * 4);
        }
        __syncthreads();
        #pragma unroll
        for (int kk = 0; kk < 32; ++kk){
            float2 a = *(const float2*)&Ask[kk * 34 + rg * 2];
            float4 b = *(const float4*)&Bsk[kk * 68 + cg * 4];
            acc[0][0] = fmaf(a.x, b.x, acc[0][0]);
            acc[0][1] = fmaf(a.x, b.y, acc[0][1]);
            acc[0][2] = fmaf(a.x, b.z, acc[0][2]);
            acc[0][3] = fmaf(a.x, b.w, acc[0][3]);
            acc[1][0] = fmaf(a.y, b.x, acc[1][0]);
            acc[1][1] = fmaf(a.y, b.y, acc[1][1]);
            acc[1][2] = fmaf(a.y, b.z, acc[1][2]);
            acc[1][3] = fmaf(a.y, b.w, acc[1][3]);
        }
        __syncthreads();
    }
    float sc = baseScale;
    if (tauPtr) sc = INV_LN2_F / fmaxf(tauPtr[0], 0.001f);
    #pragma unroll
    for (int i = 0; i < 2; ++i)
        #pragma unroll
        for (int j = 0; j < 4; ++j){
            int m = row0 + rg * 2 + i, n = col0 + cg * 4 + j;
            float v = acc[i][j] * sc;
            if (transOut) C[(size_t)n * Mtot + m] = v;
            else          C[(size_t)m * Ntot + n] = v;
        }
}

__global__ void __launch_bounds__(256) proj_u_kernel(
        const float* __restrict__ image, const float* __restrict__ W_MV){
    gemm_body(image, W_MV, g_u, D_, B_, D_, 1.0f, (const float*)0, 0);
}
__global__ void __launch_bounds__(256) proj_v_kernel(const float* __restrict__ tau){
    gemm_body(g_u, g_WMLT, g_vT, D_, B_, D_, 1.0f, tau, 1);   // writes vT[d][k]
}

// ================= main: S/ln2 = TEXT @ v^T + fused masked base-2 LSE =================
// BK=16. A tile stored in smem pre-duplicated (ull per scalar), stride 17 ull.
// B triple-buffered via cp.async; A double-buffered via LDG regs + STS.
#define BFLOATS 4096                      // 16*256 floats per B buffer
#define AULL    (64 * 17)                 // per A buffer (ull)
#define SMEM_BYTES (3 * BFLOATS * 4 + 2 * AULL * 8)   // 66560

__global__ void __launch_bounds__(256, 2) main_kernel(const float* __restrict__ text){
    extern __shared__ float sm[];
    float* Bbuf[3] = { sm, sm + BFLOATS, sm + 2 * BFLOATS };
    ull* Abase = (ull*)(sm + 3 * BFLOATS);
    ull* Abuf[2] = { Abase, Abase + AULL };

    const int tid   = threadIdx.x;
    const int blk   = blockIdx.x;
    const int r0    = blk * 64;
    const int i_blk = blk >> 3;
    const int ty    = tid >> 5;
    const int tx    = tid & 31;
    const int arow  = tid >> 2;            // 0..63
    const int aq    = tid & 3;             // quad of 4 floats

    ull acc[8][4];
    #pragma unroll
    for (int j = 0; j < 8; ++j)
        #pragma unroll
        for (int c = 0; c < 4; ++c) acc[j][c] = 0ULL;

    // ---- prologue ----
    float4 areg[2];
    areg[0] = *(const float4*)(text + (size_t)(r0 + arow) * D_ + aq * 4);
    areg[1] = *(const float4*)(text + (size_t)(r0 + arow) * D_ + 16 + aq * 4);
    {   // STS dup A0
        const float* pv = (const float*)&areg[0];
        int base = arow * 17 + aq * 4;
        #pragma unroll
        for (int t = 0; t < 4; ++t) Abuf[0][base + t] = pk2(pv[t]);
    }
    #pragma unroll
    for (int half = 0; half < 2; ++half){   // B0, B1
        float* Bd = Bbuf[half];
        int k0 = half * 16;
        #pragma unroll
        for (int it = 0; it < 4; ++it){
            int f = tid * 4 + it; int kk = f >> 6, j4 = (f & 63) * 4;
            cp16(Bd + kk * 256 + j4, g_vT + (size_t)(k0 + kk) * B_ + j4);
        }
        asm volatile("cp.async.commit_group;":::"memory");
    }

    int bcur = 0;
    #pragma unroll 1
    for (int itn = 0; itn < 32; ++itn){
        if (itn < 31) asm volatile("cp.async.wait_group 1;":::"memory");
        else          asm volatile("cp.async.wait_group 0;":::"memory");
        __syncthreads();
        if (itn + 1 < 32){
            const float* pv = (const float*)&areg[(itn + 1) & 1];
            ull* Ad = Abuf[(itn + 1) & 1];
            int base = arow * 17 + aq * 4;
            #pragma unroll
            for (int t = 0; t < 4; ++t) Ad[base + t] = pk2(pv[t]);
        }
        if (itn + 2 < 32){
            int k0 = (itn + 2) * 16;
            areg[(itn + 2) & 1] = *(const float4*)(text + (size_t)(r0 + arow) * D_ + k0 + aq * 4);
            int bfill = bcur + 2; if (bfill >= 3) bfill -= 3;
            float* Bd = Bbuf[bfill];
            #pragma unroll
            for (int it = 0; it < 4; ++it){
                int f = tid * 4 + it; int kk = f >> 6, j4 = (f & 63) * 4;
                cp16(Bd + kk * 256 + j4, g_vT + (size_t)(k0 + kk) * B_ + j4);
            }
            asm volatile("cp.async.commit_group;":::"memory");
        }
        const ull* Ad = Abuf[itn & 1];
        const ulonglong2* Bv = (const ulonglong2*)Bbuf[bcur];
        #pragma unroll
        for (int kk = 0; kk < 16; ++kk){
            ull a2[8];
            #pragma unroll
            for (int j = 0; j < 8; ++j) a2[j] = Ad[(ty * 8 + j) * 17 + kk];  // warp-uniform LDS.64
            #pragma unroll
            for (int g = 0; g < 2; ++g){
                ulonglong2 bb = Bv[kk * 64 + g * 32 + tx];                   // LDS.128
                #pragma unroll
                for (int j = 0; j < 8; ++j){
                    acc[j][g*2]   = f2fma(a2[j], bb.x, acc[j][g*2]);
                    acc[j][g*2+1] = f2fma(a2[j], bb.y, acc[j][g*2+1]);
                }
            }
        }
        if (++bcur == 3) bcur = 0;
    }
    __syncthreads();

    // -------- epilogue (smem reuse), base-2 domain --------
    unsigned* smk  = (unsigned*)sm;   // 512 mask words (64 rows x 8)
    float*    wmx  = sm + 512;        // 8 per-warp shifts
    float*    stage= sm + 528;        // 8 x 256 column partials

    smk[tid]       = g_maskT[(blk & 7) * 512 + tid];
    smk[tid + 256] = g_maskT[(blk & 7) * 512 + 256 + tid];
    __syncthreads();

    const int sg = i_blk >> 7, srem = i_blk & 127;
    const bool sown = (tx == (srem >> 2));
    const int  scc  = sg * 4 + (srem & 3);

    // pass 1: per-row full max (valid shift for everything), s_iji
    float mr[8];
    #pragma unroll
    for (int j = 0; j < 8; ++j){
        float f[8];
        #pragma unroll
        for (int c = 0; c < 4; ++c) upk(acc[j][c], f[c*2], f[c*2+1]);
        float mx = f[0];
        #pragma unroll
        for (int c = 1; c < 8; ++c) mx = fmaxf(mx, f[c]);
        #pragma unroll
        for (int o = 16; o >= 1; o >>= 1) mx = fmaxf(mx, __shfl_xor_sync(0xffffffffu, mx, o));
        mr[j] = mx;
        if (sown) g_siji[r0 + ty * 8 + j] = f[scc];
    }
    float Mw = mr[0];
    #pragma unroll
    for (int j = 1; j < 8; ++j) Mw = fmaxf(Mw, mr[j]);

    // pass 2: ONE exp2 per element serves row-LSE (k-mask) and column partials (row-valid)
    float colacc[8];
    #pragma unroll
    for (int c = 0; c < 8; ++c) colacc[c] = 0.f;
    const int iw = i_blk >> 5, ib = i_blk & 31;

    #pragma unroll
    for (int j = 0; j < 8; ++j){
        int R = ty * 8 + j;
        unsigned w0 = smk[R*8 + (tx >> 3)];
        unsigned w1 = smk[R*8 + 4 + (tx >> 3)];
        float rv = (float)((smk[R*8 + iw] >> ib) & 1u);
        float f[8];
        #pragma unroll
        for (int c = 0; c < 4; ++c) upk(acc[j][c], f[c*2], f[c*2+1]);
        float rsum = 0.f;
        #pragma unroll
        for (int c = 0; c < 8; ++c){
            float e = exp2f(f[c] - Mw);
            unsigned wg = (c < 4) ? w0 : w1;
            int q = c & 3;
            unsigned bit = (wg >> ((tx & 7) * 4 + q)) & 1u;
            rsum += bit ? e : 0.f;
            colacc[c] += rv * e;
        }
        #pragma unroll
        for (int o = 16; o >= 1; o >>= 1) rsum += __shfl_xor_sync(0xffffffffu, rsum, o);
        if (tx == 0) g_denom[r0 + R] = Mw + log2f(rsum);
    }

    if (tx == 0) wmx[ty] = Mw;
    #pragma unroll
    for (int c = 0; c < 8; ++c){
        int g = c >> 2, q = c & 3;
        stage[ty * 256 + g * 128 + tx * 4 + q] = colacc[c];
    }
    __syncthreads();

    {
        float Mb = wmx[0];
        #pragma unroll
        for (int t = 1; t < 8; ++t) Mb = fmaxf(Mb, wmx[t]);
        float S = 0.f;
        #pragma unroll
        for (int t = 0; t < 8; ++t) S += stage[t * 256 + tid] * exp2f(wmx[t] - Mb);
        g_ps[(size_t)tid * NBLK + blk] = S;
        if (tid == 0) g_pm[blk] = Mb;
    }
}

// ================= cross LSE per image column (skip same-batch blocks), base-2 =================
__global__ void cross_kernel(){
    int k = blockIdx.x, tid = threadIdx.x;
    float m = -INFINITY, s = 0.f;
    for (int b = tid; b < NBLK; b += 256){
        if ((b >> 3) == k) continue;
        float pm = g_pm[b], ps = g_ps[(size_t)k * NBLK + b];
        if (pm > m){ s = s * exp2f(m - pm) + ps; m = pm; }
        else       { s += ps * exp2f(pm - m); }
    }
    __shared__ float smm[256], sms[256];
    smm[tid] = m; sms[tid] = s;
    __syncthreads();
    for (int o = 128; o >= 1; o >>= 1){
        if (tid < o){
            float m1 = smm[tid], s1 = sms[tid];
            float m2 = smm[tid+o], s2 = sms[tid+o];
            if (m2 > m1){ s1 = s1 * exp2f(m1 - m2) + s2; m1 = m2; }
            else        { s1 += s2 * exp2f(m2 - m1); }
            smm[tid] = m1; sms[tid] = s1;
        }
        __syncthreads();
    }
    if (tid == 0) g_cross[k] = smm[0] + log2f(sms[0]);
}

// ================= final loss accumulation (convert base-2 -> natural) =================
__global__ void loss_kernel(){
    int tid = threadIdx.x;
    int r = blockIdx.x * 512 + tid;
    int i = r >> 9, l = r & 511;
    unsigned w = g_maskT[l*8 + (i >> 5)];
    int valid = (w >> (i & 31)) & 1;
    float ls = 0.f, lc = 0.f;
    if (valid){
        float s2 = g_siji[r], d2 = g_denom[r], c2 = g_cross[i];
        float mx = fmaxf(s2, c2), mn = fminf(s2, c2);
        float nl2 = mx + log1pf(exp2f(mn - mx)) * INV_LN2_F;   // log2(2^s2 + 2^c2)
        ls = 0.5f * LN2_F * ((d2 - s2) + (nl2 - s2));
        lc = 1.f;
    }
    __shared__ float rs[512], rc[512];
    rs[tid] = ls; rc[tid] = lc;
    __syncthreads();
    for (int o = 256; o >= 1; o >>= 1){
        if (tid < o){ rs[tid] += rs[tid+o]; rc[tid] += rc[tid+o]; }
        __syncthreads();
    }
    if (tid == 0){ g_lsum[blockIdx.x] = rs[0]; g_lcnt[blockIdx.x] = rc[0]; }
}

__global__ void finish_kernel(float* __restrict__ out){
    int tid = threadIdx.x;
    __shared__ float rs[256], rc[256];
    rs[tid] = g_lsum[tid]; rc[tid] = g_lcnt[tid];
    __syncthreads();
    for (int o = 128; o >= 1; o >>= 1){
        if (tid < o){ rs[tid] += rs[tid+o]; rc[tid] += rc[tid+o]; }
        __syncthreads();
    }
    if (tid == 0) out[0] = rs[0] / rc[0];
}

// ================= launch =================
extern "C" void kernel_launch(void* const* d_in, const int* in_sizes, int n_in,
                              void* d_out, int out_size){
    const float* text  = (const float*)d_in[0];
    const float* image = (const float*)d_in[1];
    const float* W_ML  = (const float*)d_in[2];
    const float* W_MV  = (const float*)d_in[3];
    const float* tau   = (const float*)d_in[4];
    const unsigned char* pmask = (const unsigned char*)d_in[5];
    float* out = (float*)d_out;

    detect_kernel<<<1, 256>>>(pmask);
    prep_kernel<<<1024, 256>>>(W_ML, pmask);
    proj_u_kernel<<<dim3(8, 8), 256>>>(image, W_MV);   // u = image @ W_MV^T
    proj_v_kernel<<<dim3(8, 8), 256>>>(tau);           // vT = ((u @ W_ML)/(tau*ln2))^T

    cudaFuncSetAttribute(main_kernel, cudaFuncAttributeMaxDynamicSharedMemorySize, SMEM_BYTES);
    main_kernel<<<NBLK, 256, SMEM_BYTES>>>(text);
    cross_kernel<<<256, 256>>>();
    loss_kernel<<<256, 512>>>();
    finish_kernel<<<1, 256>>>(out);
}

// round 17
// speedup vs baseline: 1.2038x; 1.1995x over previous
#include <cuda_runtime.h>
#include <cuda_bf16.h>
#include <math.h>

#define B_    256
#define L_    512
#define D_    512
#define NROWS (B_ * L_)     // 131072
#define NBLK  2048          // 64-row blocks
#define LN2_F     0.6931471805599453f
#define INV_LN2_F 1.4426950408889634f

// ---------------- device scratch (no allocs allowed) ----------------
__device__ __align__(16) float    g_u[B_ * D_];       // image_proj [k][e]
__device__ __align__(16) float    g_WMLT[D_ * D_];    // W_ML^T [d][e]
__device__ __align__(16) float    g_vT[D_ * B_];      // v^T [d][k], v = (u@W_ML)/(tau*ln2)
__device__ __align__(16) float    g_upart[4][B_ * D_];// split-K partials for u
__device__ __align__(16) float    g_vpart[4][B_ * D_];// split-K partials for v (untransposed [k][d])
__device__ unsigned g_maskT[L_ * 8];                  // per l: 256-bit valid-over-k
__device__ float    g_siji[NROWS];                    // base-2 scores
__device__ float    g_denom[NROWS];                   // base-2 LSE
__device__ float    g_pm[NBLK];                       // per-block shift (base-2)
__device__ float    g_ps[(size_t)B_ * NBLK];          // [col][blk] partial sums
__device__ float    g_cross[B_];                      // base-2
__device__ float    g_lsum[256];
__device__ float    g_lcnt[256];
__device__ int      g_mmode;

typedef unsigned long long ull;
__device__ __forceinline__ ull pk2(float x){ ull r; asm("mov.b64 %0,{%1,%1};":"=l"(r):"f"(x)); return r; }
__device__ __forceinline__ ull f2fma(ull a, ull b, ull c){
    ull d; asm("fma.rn.f32x2 %0,%1,%2,%3;":"=l"(d):"l"(a),"l"(b),"l"(c)); return d; }
__device__ __forceinline__ void upk(ull v, float& lo, float& hi){
    asm("mov.b64 {%0,%1},%2;":"=f"(lo),"=f"(hi):"l"(v)); }
__device__ __forceinline__ void cp16(void* dst, const void* src){
    unsigned d = (unsigned)__cvta_generic_to_shared(dst);
    asm volatile("cp.async.cg.shared.global [%0],[%1],16;"::"r"(d),"l"(src)); }

// ================= mask dtype detection =================
__global__ void detect_kernel(const unsigned char* __restrict__ p){
    __shared__ int c[4];
    int tid = threadIdx.x;
    if (tid < 4) c[tid] = 0;
    __syncthreads();
    int loc[4] = {0,0,0,0};
    for (int idx = tid; idx < 4096; idx += 256) if (p[idx]) loc[idx & 3] = 1;
    #pragma unroll
    for (int j = 0; j < 4; ++j) if (loc[j]) atomicOr(&c[j], 1);
    __syncthreads();
    if (tid == 0){
        int mode;
        if (c[1]) mode = 0;          // bytes at %4==1 nonzero -> uint8 bool
        else if (c[0]) mode = 1;     // only %4==0 nonzero -> int32 0/1
        else mode = 2;               // 1.0f pattern -> float32
        g_mmode = mode;
    }
}

__device__ __forceinline__ int mask_is_set(const unsigned char* p, int idx, int mode){
    if (mode == 0) return p[idx] != 0;
    if (mode == 1) return p[(size_t)idx * 4] != 0;
    return p[(size_t)idx * 4 + 2] != 0;
}

// ================= prep: transpose W_ML + build valid bitmaps =================
__global__ void prep_kernel(const float* __restrict__ W_ML,
                            const unsigned char* __restrict__ pmask){
    int t = blockIdx.x * blockDim.x + threadIdx.x;
    if (t < D_ * D_){
        int d = t >> 9, e = t & 511;
        g_WMLT[t] = W_ML[e * D_ + d];
    }
    if (t < L_ * 8){
        int mode = g_mmode;
        int l = t >> 3, w = t & 7;
        unsigned bits = 0;
        for (int kb = 0; kb < 32; ++kb){
            int k = w * 32 + kb;
            if (!mask_is_set(pmask, k * L_ + l, mode)) bits |= (1u << kb);
        }
        g_maskT[t] = bits;
    }
}

// ================= split-K NT GEMM body: 32x64 tile, K-chunk = 128 =================
// Cpart[m,n] = sum_{k in chunk} A[m,k]*B[n,k]   (no scale, no transpose)
__device__ __forceinline__ void gemm_body_split(
        const float* __restrict__ A, const float* __restrict__ Bm,
        float* __restrict__ Cpart, int K){
    __shared__ float Ask[32 * 34];
    __shared__ float Bsk[32 * 68];
    int tid = threadIdx.x;
    int row0 = blockIdx.x * 32, col0 = blockIdx.y * 64;
    int kbase = blockIdx.z * 128;
    int rg = tid >> 4, cg = tid & 15;
    int am = tid >> 3, aq = tid & 7;
    float acc[2][4] = {};
    float4 ra[2], rb0[2], rb1[2];

    ra[0]  = *(const float4*)(A  + (size_t)(row0 + am) * K + kbase + aq * 4);
    rb0[0] = *(const float4*)(Bm + (size_t)(col0 + am) * K + kbase + aq * 4);
    rb1[0] = *(const float4*)(Bm + (size_t)(col0 + 32 + am) * K + kbase + aq * 4);

    #pragma unroll 1
    for (int s = 0; s < 4; ++s){
        float4 va = ra[s & 1], vb0 = rb0[s & 1], vb1 = rb1[s & 1];
        const float* pa = (const float*)&va;
        const float* p0 = (const float*)&vb0;
        const float* p1 = (const float*)&vb1;
        #pragma unroll
        for (int t = 0; t < 4; ++t){
            Ask[(aq * 4 + t) * 34 + am]      = pa[t];
            Bsk[(aq * 4 + t) * 68 + am]      = p0[t];
            Bsk[(aq * 4 + t) * 68 + 32 + am] = p1[t];
        }
        if (s + 1 < 4){
            int k0 = kbase + (s + 1) * 32;
            ra[(s+1)&1]  = *(const float4*)(A  + (size_t)(row0 + am) * K + k0 + aq * 4);
            rb0[(s+1)&1] = *(const float4*)(Bm + (size_t)(col0 + am) * K + k0 + aq * 4);
            rb1[(s+1)&1] = *(const float4*)(Bm + (size_t)(col0 + 32 + am) * K + k0 + aq * 4);
        }
        __syncthreads();
        #pragma unroll
        for (int kk = 0; kk < 32; ++kk){
            float2 a = *(const float2*)&Ask[kk * 34 + rg * 2];
            float4 b = *(const float4*)&Bsk[kk * 68 + cg * 4];
            acc[0][0] = fmaf(a.x, b.x, acc[0][0]);
            acc[0][1] = fmaf(a.x, b.y, acc[0][1]);
            acc[0][2] = fmaf(a.x, b.z, acc[0][2]);
            acc[0][3] = fmaf(a.x, b.w, acc[0][3]);
            acc[1][0] = fmaf(a.y, b.x, acc[1][0]);
            acc[1][1] = fmaf(a.y, b.y, acc[1][1]);
            acc[1][2] = fmaf(a.y, b.z, acc[1][2]);
            acc[1][3] = fmaf(a.y, b.w, acc[1][3]);
        }
        __syncthreads();
    }
    #pragma unroll
    for (int i = 0; i < 2; ++i)
        #pragma unroll
        for (int j = 0; j < 4; ++j){
            int m = row0 + rg * 2 + i, n = col0 + cg * 4 + j;
            Cpart[(size_t)m * D_ + n] = acc[i][j];
        }
}

// Wrappers: device symbols resolved in DEVICE code (ATS host-shadow bug guard).
__global__ void __launch_bounds__(256) proj_u_split(
        const float* __restrict__ image, const float* __restrict__ W_MV){
    gemm_body_split(image, W_MV, g_upart[blockIdx.z], D_);
}
__global__ void __launch_bounds__(512) combine_u(){
    int idx = blockIdx.x * 512 + threadIdx.x;
    g_u[idx] = (g_upart[0][idx] + g_upart[1][idx]) + (g_upart[2][idx] + g_upart[3][idx]);
}
__global__ void __launch_bounds__(256) proj_v_split(){
    gemm_body_split(g_u, g_WMLT, g_vpart[blockIdx.z], D_);
}
__global__ void __launch_bounds__(512) combine_v(const float* __restrict__ tau){
    float sc = INV_LN2_F / fmaxf(tau[0], 0.001f);
    int idx = blockIdx.x * 512 + threadIdx.x;   // idx = d*256 + k
    int k = idx & 255, d = idx >> 8;
    int src = k * D_ + d;
    g_vT[idx] = sc * ((g_vpart[0][src] + g_vpart[1][src]) + (g_vpart[2][src] + g_vpart[3][src]));
}

// ================= main: S/ln2 = TEXT @ v^T + fused masked base-2 LSE =================
// PROVEN R6/R12 pipeline: BK=32, double-buffered cp.async A+B.
// Inner loop: A as float2 (2 kk per LDS.64, warp-uniform broadcast).
#define AS_STRIDE 36
#define ASZ (64 * AS_STRIDE)             // 2304 floats
#define BSZ (32 * 256)                   // 8192 floats
#define SMEM_BYTES ((2*ASZ + 2*BSZ) * 4) // 83968

__global__ void __launch_bounds__(256, 2) main_kernel(const float* __restrict__ text){
    extern __shared__ float sm[];
    float* Ab0 = sm;             float* Ab1 = sm + ASZ;
    float* Bb0 = sm + 2*ASZ;     float* Bb1 = sm + 2*ASZ + BSZ;

    const int tid   = threadIdx.x;
    const int blk   = blockIdx.x;
    const int r0    = blk * 64;
    const int i_blk = blk >> 3;
    const int ty    = tid >> 5;
    const int tx    = tid & 31;

    ull acc[8][4];
    #pragma unroll
    for (int j = 0; j < 8; ++j)
        #pragma unroll
        for (int c = 0; c < 4; ++c) acc[j][c] = 0ULL;

    // prologue: stage k0=0 into buffer 0
    #pragma unroll
    for (int it = 0; it < 2; ++it){
        int f = tid*2 + it; int m = f >> 3, kq = f & 7;
        cp16(Ab0 + m*AS_STRIDE + kq*4, text + (size_t)(r0+m)*D_ + kq*4);
    }
    #pragma unroll
    for (int it = 0; it < 8; ++it){
        int f = tid*8 + it; int kk = f >> 6, j4 = (f & 63)*4;
        cp16(Bb0 + kk*256 + j4, g_vT + (size_t)kk*B_ + j4);
    }
    asm volatile("cp.async.commit_group;":::"memory");

    for (int itn = 0; itn < 16; ++itn){
        if (itn + 1 < 16){
            int k0 = (itn+1)*32;
            float* Ad = ((itn+1)&1) ? Ab1 : Ab0;
            float* Bd = ((itn+1)&1) ? Bb1 : Bb0;
            #pragma unroll
            for (int it = 0; it < 2; ++it){
                int f = tid*2 + it; int m = f >> 3, kq = f & 7;
                cp16(Ad + m*AS_STRIDE + kq*4, text + (size_t)(r0+m)*D_ + k0 + kq*4);
            }
            #pragma unroll
            for (int it = 0; it < 8; ++it){
                int f = tid*8 + it; int kk = f >> 6, j4 = (f & 63)*4;
                cp16(Bd + kk*256 + j4, g_vT + (size_t)(k0+kk)*B_ + j4);
            }
            asm volatile("cp.async.commit_group;":::"memory");
            asm volatile("cp.async.wait_group 1;":::"memory");
        } else {
            asm volatile("cp.async.wait_group 0;":::"memory");
        }
        __syncthreads();
        const float* A = (itn & 1) ? Ab1 : Ab0;
        const ulonglong2* Bv = (const ulonglong2*)((itn & 1) ? Bb1 : Bb0);
        #pragma unroll
        for (int kk2 = 0; kk2 < 32; kk2 += 2){
            float2 av[8];
            #pragma unroll
            for (int j = 0; j < 8; ++j)
                av[j] = *(const float2*)&A[(ty*8+j)*AS_STRIDE + kk2];  // LDS.64 bcast, 2 kk
            #pragma unroll
            for (int t = 0; t < 2; ++t){
                ull a2[8];
                #pragma unroll
                for (int j = 0; j < 8; ++j) a2[j] = pk2(t ? av[j].y : av[j].x);
                const int kk = kk2 + t;
                #pragma unroll
                for (int g = 0; g < 2; ++g){
                    ulonglong2 bb = Bv[kk*64 + g*32 + tx];   // LDS.128, conflict-free
                    #pragma unroll
                    for (int j = 0; j < 8; ++j){
                        acc[j][g*2]   = f2fma(a2[j], bb.x, acc[j][g*2]);
                        acc[j][g*2+1] = f2fma(a2[j], bb.y, acc[j][g*2+1]);
                    }
                }
            }
        }
        __syncthreads();
    }

    // -------- epilogue (smem reuse), base-2 domain --------
    unsigned* smk  = (unsigned*)sm;   // 512 mask words (64 rows x 8)
    float*    wmx  = sm + 512;        // 8 per-warp shifts
    float*    stage= sm + 528;        // 8 x 256 column partials

    smk[tid]       = g_maskT[(blk & 7)*512 + tid];
    smk[tid + 256] = g_maskT[(blk & 7)*512 + 256 + tid];
    __syncthreads();

    const int sg = i_blk >> 7, srem = i_blk & 127;
    const bool sown = (tx == (srem >> 2));
    const int  scc  = sg*4 + (srem & 3);

    // pass 1: per-row full max (valid shift for everything), s_iji
    float mr[8];
    #pragma unroll
    for (int j = 0; j < 8; ++j){
        float f[8];
        #pragma unroll
        for (int c = 0; c < 4; ++c) upk(acc[j][c], f[c*2], f[c*2+1]);
        float mx = f[0];
        #pragma unroll
        for (int c = 1; c < 8; ++c) mx = fmaxf(mx, f[c]);
        #pragma unroll
        for (int o = 16; o >= 1; o >>= 1) mx = fmaxf(mx, __shfl_xor_sync(0xffffffffu, mx, o));
        mr[j] = mx;
        if (sown) g_siji[r0 + ty*8 + j] = f[scc];
    }
    float Mw = mr[0];
    #pragma unroll
    for (int j = 1; j < 8; ++j) Mw = fmaxf(Mw, mr[j]);

    // pass 2: ONE exp2 per element serves row-LSE (k-mask) and column partials (row-valid)
    float colacc[8];
    #pragma unroll
    for (int c = 0; c < 8; ++c) colacc[c] = 0.f;
    const int iw = i_blk >> 5, ib = i_blk & 31;

    #pragma unroll
    for (int j = 0; j < 8; ++j){
        int R = ty*8 + j;
        unsigned w0 = smk[R*8 + (tx >> 3)];
        unsigned w1 = smk[R*8 + 4 + (tx >> 3)];
        float rv = (float)((smk[R*8 + iw] >> ib) & 1u);
        float f[8];
        #pragma unroll
        for (int c = 0; c < 4; ++c) upk(acc[j][c], f[c*2], f[c*2+1]);
        float rsum = 0.f;
        #pragma unroll
        for (int c = 0; c < 8; ++c){
            float e = exp2f(f[c] - Mw);
            unsigned wg = (c < 4) ? w0 : w1;
            int q = c & 3;
            unsigned bit = (wg >> ((tx & 7)*4 + q)) & 1u;
            rsum += bit ? e : 0.f;
            colacc[c] += rv * e;
        }
        #pragma unroll
        for (int o = 16; o >= 1; o >>= 1) rsum += __shfl_xor_sync(0xffffffffu, rsum, o);
        if (tx == 0) g_denom[r0 + R] = Mw + log2f(rsum);
    }

    if (tx == 0) wmx[ty] = Mw;
    #pragma unroll
    for (int c = 0; c < 8; ++c){
        int g = c >> 2, q = c & 3;
        stage[ty*256 + g*128 + tx*4 + q] = colacc[c];
    }
    __syncthreads();

    {
        float Mb = wmx[0];
        #pragma unroll
        for (int t = 1; t < 8; ++t) Mb = fmaxf(Mb, wmx[t]);
        float S = 0.f;
        #pragma unroll
        for (int t = 0; t < 8; ++t) S += stage[t*256 + tid] * exp2f(wmx[t] - Mb);
        g_ps[(size_t)tid * NBLK + blk] = S;
        if (tid == 0) g_pm[blk] = Mb;
    }
}

// ================= cross LSE per image column (skip same-batch blocks), base-2 =================
__global__ void cross_kernel(){
    int k = blockIdx.x, tid = threadIdx.x;
    float m = -INFINITY, s = 0.f;
    for (int b = tid; b < NBLK; b += 256){
        if ((b >> 3) == k) continue;
        float pm = g_pm[b], ps = g_ps[(size_t)k * NBLK + b];
        if (pm > m){ s = s * exp2f(m - pm) + ps; m = pm; }
        else       { s += ps * exp2f(pm - m); }
    }
    __shared__ float smm[256], sms[256];
    smm[tid] = m; sms[tid] = s;
    __syncthreads();
    for (int o = 128; o >= 1; o >>= 1){
        if (tid < o){
            float m1 = smm[tid], s1 = sms[tid];
            float m2 = smm[tid+o], s2 = sms[tid+o];
            if (m2 > m1){ s1 = s1 * exp2f(m1 - m2) + s2; m1 = m2; }
            else        { s1 += s2 * exp2f(m2 - m1); }
            smm[tid] = m1; sms[tid] = s1;
        }
        __syncthreads();
    }
    if (tid == 0) g_cross[k] = smm[0] + log2f(sms[0]);
}

// ================= final loss accumulation (convert base-2 -> natural) =================
__global__ void loss_kernel(){
    int tid = threadIdx.x;
    int r = blockIdx.x * 512 + tid;
    int i = r >> 9, l = r & 511;
    unsigned w = g_maskT[l*8 + (i >> 5)];
    int valid = (w >> (i & 31)) & 1;
    float ls = 0.f, lc = 0.f;
    if (valid){
        float s2 = g_siji[r], d2 = g_denom[r], c2 = g_cross[i];
        float mx = fmaxf(s2, c2), mn = fminf(s2, c2);
        float nl2 = mx + log1pf(exp2f(mn - mx)) * INV_LN2_F;   // log2(2^s2 + 2^c2)
        ls = 0.5f * LN2_F * ((d2 - s2) + (nl2 - s2));
        lc = 1.f;
    }
    __shared__ float rs[512], rc[512];
    rs[tid] = ls; rc[tid] = lc;
    __syncthreads();
    for (int o = 256; o >= 1; o >>= 1){
        if (tid < o){ rs[tid] += rs[tid+o]; rc[tid] += rc[tid+o]; }
        __syncthreads();
    }
    if (tid == 0){ g_lsum[blockIdx.x] = rs[0]; g_lcnt[blockIdx.x] = rc[0]; }
}

__global__ void finish_kernel(float* __restrict__ out){
    int tid = threadIdx.x;
    __shared__ float rs[256], rc[256];
    rs[tid] = g_lsum[tid]; rc[tid] = g_lcnt[tid];
    __syncthreads();
    for (int o = 128; o >= 1; o >>= 1){
        if (tid < o){ rs[tid] += rs[tid+o]; rc[tid] += rc[tid+o]; }
        __syncthreads();
    }
    if (tid == 0) out[0] = rs[0] / rc[0];
}

// ================= launch =================
extern "C" void kernel_launch(void* const* d_in, const int* in_sizes, int n_in,
                              void* d_out, int out_size){
    const float* text  = (const float*)d_in[0];
    const float* image = (const float*)d_in[1];
    const float* W_ML  = (const float*)d_in[2];
    const float* W_MV  = (const float*)d_in[3];
    const float* tau   = (const float*)d_in[4];
    const unsigned char* pmask = (const unsigned char*)d_in[5];
    float* out = (float*)d_out;

    detect_kernel<<<1, 256>>>(pmask);
    prep_kernel<<<1024, 256>>>(W_ML, pmask);
    proj_u_split<<<dim3(8, 8, 4), 256>>>(image, W_MV);  // u partials
    combine_u<<<256, 512>>>();                          // u = sum of partials
    proj_v_split<<<dim3(8, 8, 4), 256>>>();             // v partials (from g_u)
    combine_v<<<256, 512>>>(tau);                       // vT = transpose + scale

    cudaFuncSetAttribute(main_kernel, cudaFuncAttributeMaxDynamicSharedMemorySize, SMEM_BYTES);
    main_kernel<<<NBLK, 256, SMEM_BYTES>>>(text);
    cross_kernel<<<256, 256>>>();
    loss_kernel<<<256, 512>>>();
    finish_kernel<<<1, 256>>>(out);
}